// round 3
// baseline (speedup 1.0000x reference)
#include <cuda_runtime.h>
#include <cstdint>

#define N_NODES 100000
#define N_EDGES 1600000
#define N_GRAPHS 512
#define NHID 128
#define NLAYER 3

// ---------------- scratch (static device arrays; no allocation) -------------
__device__ __align__(16) float g_z[(size_t)N_NODES * NHID];   // agg/z (51.2 MB)
__device__ __align__(16) float g_h[(size_t)N_NODES * NHID];   // layer out
__device__ __align__(16) float g_pool[N_GRAPHS * NHID];
__device__ int g_idx64;   // 1 if index tensors are int64, 0 if int32

// ---------------- helpers ---------------------------------------------------
__device__ __forceinline__ void red_add_v4(float* addr, float4 v) {
    asm volatile("red.global.add.v4.f32 [%0], {%1,%2,%3,%4};"
                 :: "l"(addr), "f"(v.x), "f"(v.y), "f"(v.z), "f"(v.w)
                 : "memory");
}

// ---------------- kernels ---------------------------------------------------

// Detect index width from edge_index (unsorted, values in [0, 1e5) << 2^31):
// int64 layout -> every odd 32-bit word is zero.
__global__ void detect_kernel(const int* __restrict__ ei_raw) {
    if (threadIdx.x == 0) {
        int odd = 0;
        for (int i = 0; i < 64; i++) odd |= ei_raw[2 * i + 1];
        g_idx64 = (odd == 0) ? 1 : 0;
    }
}

__global__ void copy_kernel(const float4* __restrict__ src, float4* __restrict__ dst, int n4) {
    int i = blockIdx.x * blockDim.x + threadIdx.x;
    if (i < n4) dst[i] = src[i];
}

// agg[dst] += h[src] over all edges; 32 threads (float4 lanes) per edge
__global__ void scatter_kernel(const float* __restrict__ h,
                               const void* __restrict__ ei_raw,
                               float* __restrict__ agg) {
    int t = blockIdx.x * blockDim.x + threadIdx.x;   // < N_EDGES*32
    int e = t >> 5;
    int c = (t & 31) << 2;
    int s, d;
    if (g_idx64) {
        const long long* ei = (const long long*)ei_raw;
        s = (int)ei[e];
        d = (int)ei[N_EDGES + e];
    } else {
        const int* ei = (const int*)ei_raw;
        s = ei[e];
        d = ei[N_EDGES + e];
    }
    float4 v = *(const float4*)(h + (size_t)s * NHID + c);
    red_add_v4(agg + (size_t)d * NHID + c, v);
}

// fused 2-layer MLP: hout = relu( relu(z@W1^T+b1) @ W2^T + b2 )
#define SP 132
#define SMEM_FLOATS (128*SP*2 + 64*SP*2 + 256)
#define SMEM_BYTES  (SMEM_FLOATS * 4)

__device__ __forceinline__ void gemm_tile(const float* __restrict__ A,   // [64][SP]
                                          const float* __restrict__ Ws,  // [128][SP]
                                          const float* __restrict__ bias,// [128] smem
                                          float acc[8][4], int r0, int j0) {
#pragma unroll
    for (int i = 0; i < 8; i++)
#pragma unroll
        for (int n = 0; n < 4; n++) acc[i][n] = bias[j0 + n];

#pragma unroll 2
    for (int k4 = 0; k4 < 32; k4++) {
        float4 wv[4];
#pragma unroll
        for (int n = 0; n < 4; n++)
            wv[n] = *(const float4*)(Ws + (j0 + n) * SP + k4 * 4);
#pragma unroll
        for (int i = 0; i < 8; i++) {
            float4 zv = *(const float4*)(A + (r0 + i) * SP + k4 * 4);
#pragma unroll
            for (int n = 0; n < 4; n++) {
                acc[i][n] += zv.x * wv[n].x;
                acc[i][n] += zv.y * wv[n].y;
                acc[i][n] += zv.z * wv[n].z;
                acc[i][n] += zv.w * wv[n].w;
            }
        }
    }
}

__global__ __launch_bounds__(256, 1)
void mlp_kernel(const float* __restrict__ zin,
                const float* __restrict__ W1, const float* __restrict__ b1,
                const float* __restrict__ W2, const float* __restrict__ b2,
                float* __restrict__ hout) {
    extern __shared__ float sm[];
    float* W1s = sm;                         // [128][SP]
    float* W2s = sm + 128 * SP;              // [128][SP]
    float* zt  = sm + 256 * SP;              // [64][SP]
    float* tt  = sm + 256 * SP + 64 * SP;    // [64][SP]
    float* b1s = sm + 256 * SP + 128 * SP;
    float* b2s = b1s + 128;

    int tid = threadIdx.x;

    const float4* W1v = (const float4*)W1;
    const float4* W2v = (const float4*)W2;
    for (int i = tid; i < 4096; i += 256) {
        int r = i >> 5, c4 = i & 31;
        *(float4*)(W1s + r * SP + c4 * 4) = W1v[i];
        *(float4*)(W2s + r * SP + c4 * 4) = W2v[i];
    }
    if (tid < 128) { b1s[tid] = b1[tid]; b2s[tid] = b2[tid]; }

    int row0 = blockIdx.x * 64;
    for (int i = tid; i < 64 * 32; i += 256) {
        int r = i >> 5, c4 = i & 31;
        int row = row0 + r;
        float4 v = make_float4(0.f, 0.f, 0.f, 0.f);
        if (row < N_NODES) v = *(const float4*)(zin + (size_t)row * NHID + c4 * 4);
        *(float4*)(zt + r * SP + c4 * 4) = v;
    }
    __syncthreads();

    int tx = tid & 31;
    int ty = tid >> 5;
    int j0 = tx * 4;
    int r0 = ty * 8;

    float acc[8][4];

    gemm_tile(zt, W1s, b1s, acc, r0, j0);
#pragma unroll
    for (int i = 0; i < 8; i++) {
        float4 v = make_float4(fmaxf(acc[i][0], 0.f), fmaxf(acc[i][1], 0.f),
                               fmaxf(acc[i][2], 0.f), fmaxf(acc[i][3], 0.f));
        *(float4*)(tt + (r0 + i) * SP + j0) = v;
    }
    __syncthreads();

    gemm_tile(tt, W2s, b2s, acc, r0, j0);
#pragma unroll
    for (int i = 0; i < 8; i++) {
        int row = row0 + r0 + i;
        if (row < N_NODES) {
            float4 v = make_float4(fmaxf(acc[i][0], 0.f), fmaxf(acc[i][1], 0.f),
                                   fmaxf(acc[i][2], 0.f), fmaxf(acc[i][3], 0.f));
            *(float4*)(hout + (size_t)row * NHID + j0) = v;
        }
    }
}

__global__ void pool_zero_kernel() {
    int i = blockIdx.x * blockDim.x + threadIdx.x;
    if (i < N_GRAPHS * NHID) g_pool[i] = 0.f;
}

__global__ void pool_kernel(const float* __restrict__ h,
                            const void* __restrict__ batch_raw) {
    int t = blockIdx.x * blockDim.x + threadIdx.x;   // < N_NODES*32
    int n = t >> 5;
    int c = (t & 31) << 2;
    int g;
    if (g_idx64) g = (int)((const long long*)batch_raw)[n];
    else         g = ((const int*)batch_raw)[n];
    float4 v = *(const float4*)(h + (size_t)n * NHID + c);
    red_add_v4(g_pool + g * NHID + c, v);
}

__global__ void lsm_kernel(float* __restrict__ out) {
    int r = blockIdx.x;
    int c = threadIdx.x;
    int w = c >> 5, lane = c & 31;
    __shared__ float smax[4], ssum[4];

    float v = g_pool[r * NHID + c];

    float m = v;
#pragma unroll
    for (int off = 16; off > 0; off >>= 1)
        m = fmaxf(m, __shfl_xor_sync(0xffffffffu, m, off));
    if (lane == 0) smax[w] = m;
    __syncthreads();
    m = fmaxf(fmaxf(smax[0], smax[1]), fmaxf(smax[2], smax[3]));

    float e = expf(v - m);
    float s = e;
#pragma unroll
    for (int off = 16; off > 0; off >>= 1)
        s += __shfl_xor_sync(0xffffffffu, s, off);
    if (lane == 0) ssum[w] = s;
    __syncthreads();
    s = ssum[0] + ssum[1] + ssum[2] + ssum[3];

    out[r * NHID + c] = (v - m) - logf(s);
}

// ---------------- launch -----------------------------------------------------
extern "C" void kernel_launch(void* const* d_in, const int* in_sizes, int n_in,
                              void* d_out, int out_size) {
    // Resolve inputs by element count (robust to metadata ordering).
    const float* x     = nullptr;
    const void*  ei    = nullptr;
    const void*  batch = nullptr;
    const float *W1 = nullptr, *b1 = nullptr, *W2 = nullptr, *b2 = nullptr;

    for (int i = 0; i < n_in; i++) {
        int sz = in_sizes[i];
        if (sz == N_NODES * NHID)            x = (const float*)d_in[i];
        else if (sz == 2 * N_EDGES)          ei = d_in[i];
        else if (sz == N_NODES)              batch = d_in[i];
        else if (sz == NLAYER * NHID * NHID) { if (!W1) W1 = (const float*)d_in[i]; else W2 = (const float*)d_in[i]; }
        else if (sz == NLAYER * NHID)        { if (!b1) b1 = (const float*)d_in[i]; else b2 = (const float*)d_in[i]; }
    }
    float* out = (float*)d_out;

    float *zp = nullptr, *hp = nullptr;
    cudaGetSymbolAddress((void**)&zp, g_z);
    cudaGetSymbolAddress((void**)&hp, g_h);

    cudaFuncSetAttribute(mlp_kernel, cudaFuncAttributeMaxDynamicSharedMemorySize, SMEM_BYTES);

    const int n4 = N_NODES * NHID / 4;               // 3,200,000
    const int copy_blocks    = n4 / 256;             // 12500
    const int scatter_blocks = (N_EDGES * 32) / 256; // 200000
    const int mlp_blocks     = (N_NODES + 63) / 64;  // 1563
    const int pool_blocks    = (N_NODES * 32) / 256; // 12500

    detect_kernel<<<1, 32>>>((const int*)ei);

    const float* hin = x;
    for (int l = 0; l < NLAYER; l++) {
        copy_kernel<<<copy_blocks, 256>>>((const float4*)hin, (float4*)zp, n4);
        scatter_kernel<<<scatter_blocks, 256>>>(hin, ei, zp);
        mlp_kernel<<<mlp_blocks, 256, SMEM_BYTES>>>(
            zp, W1 + l * NHID * NHID, b1 + l * NHID,
            W2 + l * NHID * NHID, b2 + l * NHID, hp);
        hin = hp;
    }

    pool_zero_kernel<<<(N_GRAPHS * NHID + 255) / 256, 256>>>();
    pool_kernel<<<pool_blocks, 256>>>(hp, batch);
    lsm_kernel<<<N_GRAPHS, NHID>>>(out);
}

// round 4
// speedup vs baseline: 1.3226x; 1.3226x over previous
#include <cuda_runtime.h>
#include <cstdint>

#define N_NODES 100000
#define N_EDGES 1600000
#define N_GRAPHS 512
#define NHID 128
#define NLAYER 3

// ---------------- scratch (static device arrays; no allocation) -------------
__device__ __align__(16) float g_z[(size_t)N_NODES * NHID];   // agg buffer
__device__ __align__(16) float g_h[(size_t)N_NODES * NHID];   // layer out
__device__ __align__(16) float g_pool[N_GRAPHS * NHID];
__device__ int g_idx64;   // 1 if index tensors are int64, 0 if int32

// ---------------- helpers ---------------------------------------------------
__device__ __forceinline__ void red_add_v4(float* addr, float4 v) {
    asm volatile("red.global.add.v4.f32 [%0], {%1,%2,%3,%4};"
                 :: "l"(addr), "f"(v.x), "f"(v.y), "f"(v.z), "f"(v.w)
                 : "memory");
}

// ---------------- kernels ---------------------------------------------------

// Detect index width from edge_index (unsorted node ids << 2^31):
// int64 layout -> every odd 32-bit word is zero.
__global__ void detect_kernel(const int* __restrict__ ei_raw) {
    if (threadIdx.x == 0) {
        int odd = 0;
        for (int i = 0; i < 64; i++) odd |= ei_raw[2 * i + 1];
        g_idx64 = (odd == 0) ? 1 : 0;
    }
}

__global__ void zero_kernel(float4* __restrict__ dst, int n4) {
    int i = blockIdx.x * blockDim.x + threadIdx.x;
    if (i < n4) dst[i] = make_float4(0.f, 0.f, 0.f, 0.f);
}

// agg[dst] += h[src]; one warp per edge, one float4 lane per thread
__global__ void scatter_kernel(const float* __restrict__ h,
                               const void* __restrict__ ei_raw,
                               float* __restrict__ agg) {
    int t = blockIdx.x * blockDim.x + threadIdx.x;   // < N_EDGES*32
    int e = t >> 5;
    int c = (t & 31) << 2;
    int s, d;
    if (g_idx64) {
        const long long* ei = (const long long*)ei_raw;
        s = (int)ei[e];
        d = (int)ei[N_EDGES + e];
    } else {
        const int* ei = (const int*)ei_raw;
        s = ei[e];
        d = ei[N_EDGES + e];
    }
    float4 v = *(const float4*)(h + (size_t)s * NHID + c);
    red_add_v4(agg + (size_t)d * NHID + c, v);
}

// ---------------- fused 2-layer MLP -----------------------------------------
// hout = relu( relu((agg+h)@W1^T+b1) @ W2^T + b2 )
// 256 threads, 64-row x 128-col tile, thread tile 4 rows x 8 cols.
// Columns per thread: {tx, tx+16, ..., tx+112} (tx = tid & 15) -> LDS.128 of
// W rows has phase bank stride SP=132 == 4 (mod 32): 8 lanes x 4 words cover
// all 32 banks -> conflict-free.
// Only ONE weight matrix staged at a time (W1, then W2) -> 103 KB smem,
// 2 CTAs/SM.
#define SP 132
#define MLP_SMEM_FLOATS (128*SP + 64*SP + 256)
#define MLP_SMEM_BYTES  (MLP_SMEM_FLOATS * 4)

__global__ __launch_bounds__(256, 2)
void mlp_kernel(const float* __restrict__ agg, const float* __restrict__ hin,
                const float* __restrict__ W1, const float* __restrict__ b1,
                const float* __restrict__ W2, const float* __restrict__ b2,
                float* __restrict__ hout) {
    extern __shared__ float sm[];
    float* Ws  = sm;                 // [128][SP]  (W1, then W2)
    float* zt  = sm + 128 * SP;      // [64][SP]   (z, then t)
    float* b1s = sm + 128 * SP + 64 * SP;
    float* b2s = b1s + 128;

    const int tid = threadIdx.x;
    const int tx = tid & 15;         // 16 col-threads, 8 cols each
    const int ty = tid >> 4;         // 16 row-groups, 4 rows each
    const int r0 = ty * 4;
    const int row0 = blockIdx.x * 64;

    // stage W1 + biases
    {
        const float4* Wv = (const float4*)W1;
        for (int i = tid; i < 4096; i += 256) {
            int r = i >> 5, c4 = i & 31;
            *(float4*)(Ws + r * SP + c4 * 4) = Wv[i];
        }
        if (tid < 128) { b1s[tid] = b1[tid]; b2s[tid] = b2[tid]; }
    }
    // stage z = agg + h
    for (int i = tid; i < 64 * 32; i += 256) {
        int r = i >> 5, c4 = i & 31;
        int row = row0 + r;
        float4 v = make_float4(0.f, 0.f, 0.f, 0.f);
        if (row < N_NODES) {
            float4 a = *(const float4*)(agg + (size_t)row * NHID + c4 * 4);
            float4 h = *(const float4*)(hin + (size_t)row * NHID + c4 * 4);
            v = make_float4(a.x + h.x, a.y + h.y, a.z + h.z, a.w + h.w);
        }
        *(float4*)(zt + r * SP + c4 * 4) = v;
    }
    __syncthreads();

    float acc[4][8];

    // ---- GEMM1 ----
#pragma unroll
    for (int i = 0; i < 4; i++)
#pragma unroll
        for (int c = 0; c < 8; c++) acc[i][c] = b1s[tx + 16 * c];

#pragma unroll 4
    for (int k4 = 0; k4 < 32; k4++) {
        float4 wv[8];
#pragma unroll
        for (int c = 0; c < 8; c++)
            wv[c] = *(const float4*)(Ws + (tx + 16 * c) * SP + k4 * 4);
        float4 zv[4];
#pragma unroll
        for (int i = 0; i < 4; i++)
            zv[i] = *(const float4*)(zt + (r0 + i) * SP + k4 * 4);
#pragma unroll
        for (int i = 0; i < 4; i++)
#pragma unroll
            for (int c = 0; c < 8; c++) {
                acc[i][c] += zv[i].x * wv[c].x;
                acc[i][c] += zv[i].y * wv[c].y;
                acc[i][c] += zv[i].z * wv[c].z;
                acc[i][c] += zv[i].w * wv[c].w;
            }
    }
#pragma unroll
    for (int i = 0; i < 4; i++)
#pragma unroll
        for (int c = 0; c < 8; c++) acc[i][c] = fmaxf(acc[i][c], 0.f);

    __syncthreads();   // all GEMM1 reads of Ws/zt done

    // write t over zt; restage Ws with W2
#pragma unroll
    for (int i = 0; i < 4; i++)
#pragma unroll
        for (int c = 0; c < 8; c++)
            zt[(r0 + i) * SP + tx + 16 * c] = acc[i][c];
    {
        const float4* Wv = (const float4*)W2;
        for (int i = tid; i < 4096; i += 256) {
            int r = i >> 5, c4 = i & 31;
            *(float4*)(Ws + r * SP + c4 * 4) = Wv[i];
        }
    }
    __syncthreads();

    // ---- GEMM2 ----
#pragma unroll
    for (int i = 0; i < 4; i++)
#pragma unroll
        for (int c = 0; c < 8; c++) acc[i][c] = b2s[tx + 16 * c];

#pragma unroll 4
    for (int k4 = 0; k4 < 32; k4++) {
        float4 wv[8];
#pragma unroll
        for (int c = 0; c < 8; c++)
            wv[c] = *(const float4*)(Ws + (tx + 16 * c) * SP + k4 * 4);
        float4 zv[4];
#pragma unroll
        for (int i = 0; i < 4; i++)
            zv[i] = *(const float4*)(zt + (r0 + i) * SP + k4 * 4);
#pragma unroll
        for (int i = 0; i < 4; i++)
#pragma unroll
            for (int c = 0; c < 8; c++) {
                acc[i][c] += zv[i].x * wv[c].x;
                acc[i][c] += zv[i].y * wv[c].y;
                acc[i][c] += zv[i].z * wv[c].z;
                acc[i][c] += zv[i].w * wv[c].w;
            }
    }

    // relu + store (scalar, coalesced within half-warp)
#pragma unroll
    for (int i = 0; i < 4; i++) {
        int row = row0 + r0 + i;
        if (row < N_NODES) {
#pragma unroll
            for (int c = 0; c < 8; c++)
                hout[(size_t)row * NHID + tx + 16 * c] = fmaxf(acc[i][c], 0.f);
        }
    }
}

__global__ void pool_zero_kernel() {
    int i = blockIdx.x * blockDim.x + threadIdx.x;
    if (i < N_GRAPHS * NHID) g_pool[i] = 0.f;
}

__global__ void pool_kernel(const float* __restrict__ h,
                            const void* __restrict__ batch_raw) {
    int t = blockIdx.x * blockDim.x + threadIdx.x;   // < N_NODES*32
    int n = t >> 5;
    int c = (t & 31) << 2;
    int g;
    if (g_idx64) g = (int)((const long long*)batch_raw)[n];
    else         g = ((const int*)batch_raw)[n];
    float4 v = *(const float4*)(h + (size_t)n * NHID + c);
    red_add_v4(g_pool + g * NHID + c, v);
}

__global__ void lsm_kernel(float* __restrict__ out) {
    int r = blockIdx.x;
    int c = threadIdx.x;
    int w = c >> 5, lane = c & 31;
    __shared__ float smax[4], ssum[4];

    float v = g_pool[r * NHID + c];

    float m = v;
#pragma unroll
    for (int off = 16; off > 0; off >>= 1)
        m = fmaxf(m, __shfl_xor_sync(0xffffffffu, m, off));
    if (lane == 0) smax[w] = m;
    __syncthreads();
    m = fmaxf(fmaxf(smax[0], smax[1]), fmaxf(smax[2], smax[3]));

    float e = expf(v - m);
    float s = e;
#pragma unroll
    for (int off = 16; off > 0; off >>= 1)
        s += __shfl_xor_sync(0xffffffffu, s, off);
    if (lane == 0) ssum[w] = s;
    __syncthreads();
    s = ssum[0] + ssum[1] + ssum[2] + ssum[3];

    out[r * NHID + c] = (v - m) - logf(s);
}

// ---------------- launch -----------------------------------------------------
extern "C" void kernel_launch(void* const* d_in, const int* in_sizes, int n_in,
                              void* d_out, int out_size) {
    // Resolve inputs by element count (robust to metadata ordering).
    const float* x     = nullptr;
    const void*  ei    = nullptr;
    const void*  batch = nullptr;
    const float *W1 = nullptr, *b1 = nullptr, *W2 = nullptr, *b2 = nullptr;

    for (int i = 0; i < n_in; i++) {
        int sz = in_sizes[i];
        if (sz == N_NODES * NHID)            x = (const float*)d_in[i];
        else if (sz == 2 * N_EDGES)          ei = d_in[i];
        else if (sz == N_NODES)              batch = d_in[i];
        else if (sz == NLAYER * NHID * NHID) { if (!W1) W1 = (const float*)d_in[i]; else W2 = (const float*)d_in[i]; }
        else if (sz == NLAYER * NHID)        { if (!b1) b1 = (const float*)d_in[i]; else b2 = (const float*)d_in[i]; }
    }
    float* out = (float*)d_out;

    float *zp = nullptr, *hp = nullptr;
    cudaGetSymbolAddress((void**)&zp, g_z);
    cudaGetSymbolAddress((void**)&hp, g_h);

    cudaFuncSetAttribute(mlp_kernel, cudaFuncAttributeMaxDynamicSharedMemorySize, MLP_SMEM_BYTES);

    const int n4 = N_NODES * NHID / 4;               // 3,200,000
    const int zero_blocks    = n4 / 256;             // 12500
    const int scatter_blocks = (N_EDGES * 32) / 256; // 200000
    const int mlp_blocks     = (N_NODES + 63) / 64;  // 1563
    const int pool_blocks    = (N_NODES * 32) / 256; // 12500

    detect_kernel<<<1, 32>>>((const int*)ei);

    const float* hin = x;
    for (int l = 0; l < NLAYER; l++) {
        zero_kernel<<<zero_blocks, 256>>>((float4*)zp, n4);
        scatter_kernel<<<scatter_blocks, 256>>>(hin, ei, zp);
        mlp_kernel<<<mlp_blocks, 256, MLP_SMEM_BYTES>>>(
            zp, hin, W1 + l * NHID * NHID, b1 + l * NHID,
            W2 + l * NHID * NHID, b2 + l * NHID, hp);
        hin = hp;
    }

    pool_zero_kernel<<<(N_GRAPHS * NHID + 255) / 256, 256>>>();
    pool_kernel<<<pool_blocks, 256>>>(hp, batch);
    lsm_kernel<<<N_GRAPHS, NHID>>>(out);
}